// round 8
// baseline (speedup 1.0000x reference)
#include <cuda_runtime.h>
#include <cstdint>
#include <cstddef>

#define Bc 16
#define Nc 4096
#define Cc 512
#define Mc 32
#define ITERS 50
#define MU_ (1.0f/4096.0f)
#define OUT0 ((size_t)Bc*Nc*Cc)

// ---------------- device scratch (statics: the sanctioned no-alloc scratch) ----------------
static __device__ float g_yn[Bc*Mc*Cc];            // normalized target rows
static __device__ float g_Yt[Bc*Mc*Cc];            // target @ W_bot
static __device__ float g_cost[(size_t)Bc*Nc*Mc];  // 1 - cosine
static __device__ float g_K[(size_t)Bc*Nc*Mc];     // exp(-cost/0.05)
static __device__ float g_nu[Bc*Mc];
static __device__ int   g_counts[Bc*Mc];
static __device__ float g_vhist[Bc*ITERS*Mc];
static __device__ float g_errhist[Bc*ITERS];
static __device__ float g_vfin[Bc*Mc];
static __device__ float g_vprev[Bc*Mc];
static __device__ float g_pn[(size_t)Bc*Nc*Mc];    // pi_norm
static __device__ float g_otPart[Bc*8];
static __device__ float g_H[(size_t)Bc*Nc*Cc];     // pre-LN activations

__device__ __forceinline__ float wsum(float v) {
    v += __shfl_xor_sync(0xffffffffu, v, 16);
    v += __shfl_xor_sync(0xffffffffu, v, 8);
    v += __shfl_xor_sync(0xffffffffu, v, 4);
    v += __shfl_xor_sync(0xffffffffu, v, 2);
    v += __shfl_xor_sync(0xffffffffu, v, 1);
    return v;
}

// ---------------- reset persistent accumulators (re-run every replay) ----------------
__global__ void reset_kernel() {
    int tid = threadIdx.x;
    if (tid < Bc*Mc) g_counts[tid] = 0;
}

// ---------------- nu: argmax histogram over score_map [B,K,H,W] ----------------
__global__ void hist_kernel(const float* __restrict__ score) {
    __shared__ int h[Mc];
    int b = blockIdx.x >> 4, chunk = blockIdx.x & 15;
    int tid = threadIdx.x;
    if (tid < Mc) h[tid] = 0;
    __syncthreads();
    int p = chunk*256 + tid;
    const float* s = score + (size_t)b*Mc*Nc + p;
    float best = s[0]; int bi = 0;
#pragma unroll
    for (int k = 1; k < Mc; k++) {
        float v = s[(size_t)k*Nc];
        if (v > best) { best = v; bi = k; }
    }
    atomicAdd(&h[bi], 1);
    __syncthreads();
    if (tid < Mc) atomicAdd(&g_counts[b*Mc + tid], h[tid]);
}

__global__ void nu_kernel() {
    int tid = threadIdx.x;                 // 512 threads: warp = batch
    int b = tid >> 5, m = tid & 31;
    float c = (float)g_counts[b*Mc + m];
    float total = wsum(c);
    float nu1 = c / (total + 1e-8f);
    float nu2 = nu1 + 1e-6f;
    float s2 = wsum(nu2);
    g_nu[b*Mc + m] = nu2 / s2;
}

// ---------------- target row-normalize ----------------
__global__ void yn_kernel(const float* __restrict__ tgt) {
    int b = blockIdx.x;
    int w = threadIdx.x >> 5, lane = threadIdx.x & 31;   // 16 warps
    for (int m = w; m < Mc; m += 16) {
        const float* y = tgt + ((size_t)(b*Mc + m))*Cc;
        float ss = 0.f;
        for (int j = lane*4; j < Cc; j += 128) {
            float4 v = *(const float4*)(y + j);
            ss += v.x*v.x + v.y*v.y + v.z*v.z + v.w*v.w;
        }
        ss = wsum(ss);
        float inv = rsqrtf(ss);
        for (int j = lane*4; j < Cc; j += 128) {
            float4 v = *(const float4*)(y + j);
            float4 o; o.x = v.x*inv; o.y = v.y*inv; o.z = v.z*inv; o.w = v.w*inv;
            *(float4*)(g_yn + ((size_t)(b*Mc + m))*Cc + j) = o;
        }
    }
}

// ---------------- Yt = target @ W_bot  (W rows 512..1023) ----------------
__global__ void __launch_bounds__(128) yt_kernel(const float* __restrict__ tgt,
                                                 const float* __restrict__ W) {
    int b  = blockIdx.x >> 2;
    int c0 = (blockIdx.x & 3) * 128;
    int c  = c0 + threadIdx.x;
    __shared__ float st[64][33];     // [kk][m]
    float acc[Mc];
#pragma unroll
    for (int m = 0; m < Mc; m++) acc[m] = 0.f;
    for (int k0 = 0; k0 < Cc; k0 += 64) {
        __syncthreads();
        for (int i = threadIdx.x; i < 512; i += 128) {   // 32 m x 16 float4
            int m = i >> 4, kq = i & 15;
            float4 v = *(const float4*)(tgt + ((size_t)(b*Mc + m))*Cc + k0 + kq*4);
            st[kq*4+0][m] = v.x; st[kq*4+1][m] = v.y;
            st[kq*4+2][m] = v.z; st[kq*4+3][m] = v.w;
        }
        __syncthreads();
        for (int kk = 0; kk < 64; kk++) {
            float w = W[(size_t)(Cc + k0 + kk)*Cc + c];
#pragma unroll
            for (int m = 0; m < Mc; m++) acc[m] = fmaf(st[kk][m], w, acc[m]);
        }
    }
#pragma unroll
    for (int m = 0; m < Mc; m++)
        g_Yt[((size_t)(b*Mc + m))*Cc + c] = acc[m];
}

// ---------------- cost & K: per (b, 128-row tile) ----------------
__global__ void __launch_bounds__(256) cost_kernel(const float* __restrict__ src) {
    __shared__ float As[32][132];
    __shared__ float Bs[32][36];
    int b  = blockIdx.x >> 5;
    int r0 = (blockIdx.x & 31) * 128;
    int tid = threadIdx.x;
    int tx = tid & 7, ty = tid >> 3;           // tx: 8 m-groups(4), ty: 32 row-groups(4)
    float acc[4][4], accn[4];
#pragma unroll
    for (int i = 0; i < 4; i++) {
        accn[i] = 0.f;
#pragma unroll
        for (int j = 0; j < 4; j++) acc[i][j] = 0.f;
    }
    for (int k0 = 0; k0 < Cc; k0 += 32) {
        __syncthreads();
        for (int i = tid; i < 1024; i += 256) {          // 128 rows x 8 float4
            int r = i >> 3, kq = i & 7;
            float4 v = *(const float4*)(src + ((size_t)(b*Nc + r0 + r))*Cc + k0 + kq*4);
            As[kq*4+0][r] = v.x; As[kq*4+1][r] = v.y;
            As[kq*4+2][r] = v.z; As[kq*4+3][r] = v.w;
        }
        {
            int i = tid;
            if (i < 256) {                               // 32 m x 8 float4
                int m = i >> 3, kq = i & 7;
                float4 v = *(const float4*)(g_yn + ((size_t)(b*Mc + m))*Cc + k0 + kq*4);
                Bs[kq*4+0][m] = v.x; Bs[kq*4+1][m] = v.y;
                Bs[kq*4+2][m] = v.z; Bs[kq*4+3][m] = v.w;
            }
        }
        __syncthreads();
#pragma unroll
        for (int k = 0; k < 32; k++) {
            float a[4], bb[4];
#pragma unroll
            for (int i = 0; i < 4; i++) a[i] = As[k][ty*4 + i];
#pragma unroll
            for (int j = 0; j < 4; j++) bb[j] = Bs[k][tx*4 + j];
#pragma unroll
            for (int i = 0; i < 4; i++) {
                accn[i] = fmaf(a[i], a[i], accn[i]);
#pragma unroll
                for (int j = 0; j < 4; j++) acc[i][j] = fmaf(a[i], bb[j], acc[i][j]);
            }
        }
    }
#pragma unroll
    for (int i = 0; i < 4; i++) {
        int n = r0 + ty*4 + i;
        float inv = rsqrtf(accn[i]);
        float4 cv, kv;
        cv.x = 1.f - acc[i][0]*inv; cv.y = 1.f - acc[i][1]*inv;
        cv.z = 1.f - acc[i][2]*inv; cv.w = 1.f - acc[i][3]*inv;
        kv.x = expf(-cv.x/0.05f); kv.y = expf(-cv.y/0.05f);
        kv.z = expf(-cv.z/0.05f); kv.w = expf(-cv.w/0.05f);
        size_t base = ((size_t)(b*Nc + n))*Mc + tx*4;
        *(float4*)(g_cost + base) = cv;
        *(float4*)(g_K + base)    = kv;
    }
}

// ---------------- Sinkhorn: one CTA per batch, 512 threads, 8 rows/thread ----------------
__global__ void __launch_bounds__(512) sinkhorn_kernel() {
    int b   = blockIdx.x;
    int tid = threadIdx.x;
    int lane = tid & 31, wid = tid >> 5;
    __shared__ float sv[Mc];
    __shared__ float snu[Mc];
    __shared__ float sS[16][33];
    __shared__ float sErr[16];
    if (tid < Mc) { sv[tid] = 0.f; snu[tid] = g_nu[b*Mc + tid]; }
    __syncthreads();
    float u[8];
#pragma unroll
    for (int j = 0; j < 8; j++) u[j] = 0.f;
    const float4* Kb = (const float4*)(g_K + (size_t)b*Nc*Mc);
    for (int t = 0; t < ITERS; t++) {
        float vr[Mc];
#pragma unroll
        for (int m = 0; m < Mc; m++) vr[m] = sv[m];
        float S[Mc];
#pragma unroll
        for (int m = 0; m < Mc; m++) S[m] = 0.f;
        float errLoc = 0.f;
#pragma unroll
        for (int j = 0; j < 8; j++) {
            int n = j*512 + tid;
            const float4* kp = Kb + (size_t)n*8;
            float d = 0.f;
#pragma unroll
            for (int q = 0; q < 8; q++) {
                float4 v4 = kp[q];
                d = fmaf(v4.x, vr[q*4+0], d);
                d = fmaf(v4.y, vr[q*4+1], d);
                d = fmaf(v4.z, vr[q*4+2], d);
                d = fmaf(v4.w, vr[q*4+3], d);
            }
            float un = MU_ / (d + 1e-8f);
            errLoc += fabsf(un - u[j]);
            u[j] = un;
#pragma unroll
            for (int q = 0; q < 8; q++) {
                float4 v4 = kp[q];
                S[q*4+0] = fmaf(v4.x, un, S[q*4+0]);
                S[q*4+1] = fmaf(v4.y, un, S[q*4+1]);
                S[q*4+2] = fmaf(v4.z, un, S[q*4+2]);
                S[q*4+3] = fmaf(v4.w, un, S[q*4+3]);
            }
        }
#pragma unroll
        for (int m = 0; m < Mc; m++) S[m] = wsum(S[m]);
        errLoc = wsum(errLoc);
        if (lane == 0) {
#pragma unroll
            for (int m = 0; m < Mc; m++) sS[wid][m] = S[m];
            sErr[wid] = errLoc;
        }
        __syncthreads();
        if (tid < Mc) {
            float s = 0.f;
#pragma unroll
            for (int w = 0; w < 16; w++) s += sS[w][tid];
            float vnew = snu[tid] / (s + 1e-8f);
            sv[tid] = vnew;
            g_vhist[((size_t)b*ITERS + t)*Mc + tid] = vnew;
        }
        if (tid == 32) {
            float e = 0.f;
            for (int w = 0; w < 16; w++) e += sErr[w];
            g_errhist[b*ITERS + t] = e;
        }
        __syncthreads();
    }
}

// ---------------- pick iteration T (global early-stop), extract v_T, v_{T-1} ----------------
__global__ void pick_kernel() {
    __shared__ int sT;
    if (threadIdx.x == 0) {
        int T = ITERS - 1;
        for (int t = 0; t < ITERS; t++) {
            float e = 0.f;
            for (int b = 0; b < Bc; b++) e += g_errhist[b*ITERS + t];
            e *= (1.0f/(float)Bc);
            if (e < 0.1f) { T = t; break; }
        }
        sT = T;
    }
    __syncthreads();
    int T = sT;
    int m = threadIdx.x;
    if (m < Mc) {
        for (int b = 0; b < Bc; b++) {
            g_vfin[b*Mc + m]  = g_vhist[((size_t)b*ITERS + T)*Mc + m];
            g_vprev[b*Mc + m] = (T > 0) ? g_vhist[((size_t)b*ITERS + T - 1)*Mc + m] : 0.f;
        }
    }
}

// ---------------- finalize: u_T, pi, ot partials, pi_norm ----------------
__global__ void __launch_bounds__(256) finalize_kernel(float* __restrict__ out) {
    int b  = blockIdx.x >> 3;
    int r0 = (blockIdx.x & 7) * 512;
    __shared__ float svp[Mc], svf[Mc];
    __shared__ float red[256];
    int tid = threadIdx.x;
    if (tid < Mc) { svp[tid] = g_vprev[b*Mc + tid]; svf[tid] = g_vfin[b*Mc + tid]; }
    __syncthreads();
    float vp[Mc], vf[Mc];
#pragma unroll
    for (int m = 0; m < Mc; m++) { vp[m] = svp[m]; vf[m] = svf[m]; }
    float otLoc = 0.f;
    for (int jj = 0; jj < 2; jj++) {
        int n = r0 + jj*256 + tid;
        size_t base = ((size_t)(b*Nc + n))*Mc;
        const float4* kp = (const float4*)(g_K + base);
        const float4* cp = (const float4*)(g_cost + base);
        float kr[Mc];
#pragma unroll
        for (int q = 0; q < 8; q++) {
            float4 v = kp[q];
            kr[q*4+0] = v.x; kr[q*4+1] = v.y; kr[q*4+2] = v.z; kr[q*4+3] = v.w;
        }
        float d = 0.f;
#pragma unroll
        for (int m = 0; m < Mc; m++) d = fmaf(kr[m], vp[m], d);
        float u = MU_ / (d + 1e-8f);
        float pi[Mc]; float s = 0.f;
#pragma unroll
        for (int m = 0; m < Mc; m++) { pi[m] = u * kr[m] * vf[m]; s += pi[m]; }
#pragma unroll
        for (int q = 0; q < 8; q++) {
            float4 c4 = cp[q];
            otLoc += pi[q*4+0]*c4.x + pi[q*4+1]*c4.y + pi[q*4+2]*c4.z + pi[q*4+3]*c4.w;
        }
        float inv = 1.f/(s + 1e-8f);
        float* piOut = out + OUT0 + Bc + base;
#pragma unroll
        for (int q = 0; q < 8; q++) {
            float4 o;  o.x = pi[q*4+0]; o.y = pi[q*4+1]; o.z = pi[q*4+2]; o.w = pi[q*4+3];
            *(float4*)(piOut + q*4) = o;
            float4 pn; pn.x = o.x*inv; pn.y = o.y*inv; pn.z = o.z*inv; pn.w = o.w*inv;
            *(float4*)(g_pn + base + q*4) = pn;
        }
    }
    red[tid] = otLoc;
    __syncthreads();
    for (int s2 = 128; s2 > 0; s2 >>= 1) {
        if (tid < s2) red[tid] += red[tid + s2];
        __syncthreads();
    }
    if (tid == 0) g_otPart[blockIdx.x] = red[0];
}

__global__ void otsum_kernel(float* __restrict__ out) {
    int b = threadIdx.x;
    if (b < Bc) {
        float s = 0.f;
        for (int i = 0; i < 8; i++) s += g_otPart[b*8 + i];
        out[OUT0 + b] = s;
    }
}

// ---------------- H = [src | pn] @ [W_top ; Yt_b] + bias ----------------
__global__ void __launch_bounds__(256) gemm_kernel(const float* __restrict__ src,
                                                   const float* __restrict__ W,
                                                   const float* __restrict__ bias) {
    __shared__ float As[16][132];
    __shared__ float Bs[16][128];
    int row0 = blockIdx.x * 128;
    int c0   = blockIdx.y * 128;
    int b    = row0 >> 12;
    int tid  = threadIdx.x;
    int tx = tid & 15, ty = tid >> 4;

    float acc[8][8];
#pragma unroll
    for (int i = 0; i < 8; i++)
#pragma unroll
        for (int j = 0; j < 8; j++) acc[i][j] = 0.f;

    float4 ra[2], rb[2];
    // prologue: tile kt=0 (k0=0, always src/W region)
#pragma unroll
    for (int q = 0; q < 2; q++) {
        int idx = tid*2 + q; int r = idx >> 2, kq = idx & 3;
        ra[q] = *(const float4*)(src + ((size_t)(row0 + r))*Cc + kq*4);
        int kr = idx >> 5, cq = idx & 31;
        rb[q] = *(const float4*)(W + ((size_t)kr)*Cc + c0 + cq*4);
    }
#pragma unroll
    for (int q = 0; q < 2; q++) {
        int idx = tid*2 + q; int r = idx >> 2, kq = idx & 3;
        As[kq*4+0][r] = ra[q].x; As[kq*4+1][r] = ra[q].y;
        As[kq*4+2][r] = ra[q].z; As[kq*4+3][r] = ra[q].w;
        int kr = idx >> 5, cq = idx & 31;
        *(float4*)&Bs[kr][cq*4] = rb[q];
    }
    __syncthreads();

    for (int kt = 0; kt < 34; kt++) {
        int k0n = (kt + 1) * 16;
        if (kt + 1 < 34) {
#pragma unroll
            for (int q = 0; q < 2; q++) {
                int idx = tid*2 + q; int r = idx >> 2, kq = idx & 3;
                if (k0n < 512)
                    ra[q] = *(const float4*)(src + ((size_t)(row0 + r))*Cc + k0n + kq*4);
                else
                    ra[q] = *(const float4*)(g_pn + ((size_t)(row0 + r))*Mc + (k0n - 512) + kq*4);
                int kr = idx >> 5, cq = idx & 31;
                if (k0n < 512)
                    rb[q] = *(const float4*)(W + ((size_t)(k0n + kr))*Cc + c0 + cq*4);
                else
                    rb[q] = *(const float4*)(g_Yt + ((size_t)(b*Mc + (k0n - 512) + kr))*Cc + c0 + cq*4);
            }
        }
#pragma unroll
        for (int k = 0; k < 16; k++) {
            float a[8], bb[8];
            *(float4*)&a[0]  = *(float4*)&As[k][ty*8];
            *(float4*)&a[4]  = *(float4*)&As[k][ty*8 + 4];
            *(float4*)&bb[0] = *(float4*)&Bs[k][tx*8];
            *(float4*)&bb[4] = *(float4*)&Bs[k][tx*8 + 4];
#pragma unroll
            for (int i = 0; i < 8; i++)
#pragma unroll
                for (int j = 0; j < 8; j++)
                    acc[i][j] = fmaf(a[i], bb[j], acc[i][j]);
        }
        __syncthreads();
        if (kt + 1 < 34) {
#pragma unroll
            for (int q = 0; q < 2; q++) {
                int idx = tid*2 + q; int r = idx >> 2, kq = idx & 3;
                As[kq*4+0][r] = ra[q].x; As[kq*4+1][r] = ra[q].y;
                As[kq*4+2][r] = ra[q].z; As[kq*4+3][r] = ra[q].w;
                int kr = idx >> 5, cq = idx & 31;
                *(float4*)&Bs[kr][cq*4] = rb[q];
            }
            __syncthreads();
        }
    }

#pragma unroll
    for (int i = 0; i < 8; i++) {
        size_t g = (size_t)(row0 + ty*8 + i)*Cc + c0 + tx*8;
#pragma unroll
        for (int j4 = 0; j4 < 2; j4++) {
            float4 bv = *(const float4*)(bias + c0 + tx*8 + j4*4);
            float4 o;
            o.x = acc[i][j4*4+0] + bv.x; o.y = acc[i][j4*4+1] + bv.y;
            o.z = acc[i][j4*4+2] + bv.z; o.w = acc[i][j4*4+3] + bv.w;
            *(float4*)(g_H + g + j4*4) = o;
        }
    }
}

// ---------------- LayerNorm over C=512, one warp per row ----------------
__global__ void __launch_bounds__(256) ln_kernel(float* __restrict__ out,
                                                 const float* __restrict__ gamma,
                                                 const float* __restrict__ beta) {
    int row  = blockIdx.x*8 + (threadIdx.x >> 5);
    int lane = threadIdx.x & 31;
    const float* h = g_H + (size_t)row*Cc;
    float4 x[4];
    float s = 0.f;
#pragma unroll
    for (int q = 0; q < 4; q++) {
        x[q] = *(const float4*)(h + q*128 + lane*4);
        s += x[q].x + x[q].y + x[q].z + x[q].w;
    }
    s = wsum(s);
    float mean = s * (1.0f/512.0f);
    float var = 0.f;
#pragma unroll
    for (int q = 0; q < 4; q++) {
        float a = x[q].x - mean, b2 = x[q].y - mean, c = x[q].z - mean, d = x[q].w - mean;
        var += a*a + b2*b2 + c*c + d*d;
    }
    var = wsum(var) * (1.0f/512.0f);
    float inv = rsqrtf(var + 1e-5f);
    float* o = out + (size_t)row*Cc;
#pragma unroll
    for (int q = 0; q < 4; q++) {
        int c = q*128 + lane*4;
        float4 g4 = *(const float4*)(gamma + c);
        float4 b4 = *(const float4*)(beta + c);
        float4 r;
        r.x = (x[q].x - mean)*inv*g4.x + b4.x;
        r.y = (x[q].y - mean)*inv*g4.y + b4.y;
        r.z = (x[q].z - mean)*inv*g4.z + b4.z;
        r.w = (x[q].w - mean)*inv*g4.w + b4.w;
        *(float4*)(o + c) = r;
    }
}

// ---------------- launcher ----------------
extern "C" void kernel_launch(void* const* d_in, const int* in_sizes, int n_in,
                              void* d_out, int out_size) {
    const float* src   = (const float*)d_in[0];   // [B, N, C]
    const float* tgt   = (const float*)d_in[1];   // [B, M, C]
    const float* score = (const float*)d_in[2];   // [B, M, H, W]
    const float* W     = (const float*)d_in[3];   // [2C, C]
    const float* bias  = (const float*)d_in[4];   // [C]
    const float* gamma = (const float*)d_in[5];   // [C]
    const float* beta  = (const float*)d_in[6];   // [C]
    float* out = (float*)d_out;                   // [B*N*C | B | B*N*M]

    reset_kernel<<<1, 512>>>();
    hist_kernel<<<Bc*16, 256>>>(score);
    nu_kernel<<<1, 512>>>();
    yn_kernel<<<Bc, 512>>>(tgt);
    yt_kernel<<<Bc*4, 128>>>(tgt, W);
    cost_kernel<<<Bc*32, 256>>>(src);
    sinkhorn_kernel<<<Bc, 512>>>();
    pick_kernel<<<1, 32>>>();
    finalize_kernel<<<Bc*8, 256>>>(out);
    otsum_kernel<<<1, 32>>>(out);
    gemm_kernel<<<dim3(512, 4), 256>>>(src, W, bias);
    ln_kernel<<<8192, 256>>>(out, gamma, beta);
}